// round 12
// baseline (speedup 1.0000x reference)
#include <cuda_runtime.h>
#include <cuda_bf16.h>
#include <math.h>
#include <stdint.h>

#define BB 2
#define SS 2048
#define HH 1024
#define FF 2816
#define EE 8
#define KK 2
#define TT (BB*SS)
#define SLOTS (TT*KK)
#define BM 128
#define PADMAX (SLOTS + EE*BM)    // 9216
#define RT_MAX (PADMAX/BM)        // 72
#define PIT 136                   // uint2 pitch
#define KP_H (HH/2)               // 512 kpairs (gemm1 K)
#define KP_F (FF/2)               // 1408 kpairs (gemm2 K)

__device__ float g_h1[(size_t)PADMAX * FF];
__device__ float g_y [(size_t)PADMAX * HH];
__device__ uint2 g_px[(size_t)TT * KP_H];
__device__ uint2 g_pwgu[(size_t)EE * KP_H * 2 * FF];
__device__ uint2 g_pwd[(size_t)EE * KP_F * HH];
__device__ uint2 g_ph1[(size_t)PADMAX * KP_F];
__device__ int   g_count[EE];
__device__ int   g_fill[EE];
__device__ float g_psum[EE];
__device__ int   g_base[EE+1];
__device__ int   g_sorted_token[PADMAX];
__device__ int   g_slot_row[SLOTS];
__device__ int   g_tok_e[SLOTS];
__device__ float g_tok_w[SLOTS];

// pack two floats (k-even, k-odd) into (hi-pair, lo-pair) bf16x2 words
__device__ __forceinline__ uint2 spb(float x, float y) {
    __nv_bfloat16 hx = __float2bfloat16(x);
    __nv_bfloat16 hy = __float2bfloat16(y);
    __nv_bfloat16 lx = __float2bfloat16(x - __bfloat162float(hx));
    __nv_bfloat16 ly = __float2bfloat16(y - __bfloat162float(hy));
    uint2 r;
    r.x = (uint32_t)__bfloat16_as_ushort(hx) | ((uint32_t)__bfloat16_as_ushort(hy) << 16);
    r.y = (uint32_t)__bfloat16_as_ushort(lx) | ((uint32_t)__bfloat16_as_ushort(ly) << 16);
    return r;
}
__device__ __forceinline__ void mma_bf16(float* d, const uint32_t* a, uint32_t b0, uint32_t b1) {
    asm volatile("mma.sync.aligned.m16n8k16.row.col.f32.bf16.bf16.f32 "
                 "{%0,%1,%2,%3}, {%4,%5,%6,%7}, {%8,%9}, {%0,%1,%2,%3};"
                 : "+f"(d[0]), "+f"(d[1]), "+f"(d[2]), "+f"(d[3])
                 : "r"(a[0]), "r"(a[1]), "r"(a[2]), "r"(a[3]), "r"(b0), "r"(b1));
}
__device__ __forceinline__ uint32_t smem_u32(const void* p) {
    uint32_t a;
    asm("{ .reg .u64 t; cvta.to.shared.u64 t, %1; cvt.u32.u64 %0, t; }" : "=r"(a) : "l"(p));
    return a;
}
__device__ __forceinline__ void cp16(uint32_t dst, const void* src) {
    asm volatile("cp.async.cg.shared.global [%0], [%1], 16;"
                 :: "r"(dst), "l"(__cvta_generic_to_global(src)) : "memory");
}
__device__ __forceinline__ void cp8(uint32_t dst, const void* src) {
    asm volatile("cp.async.ca.shared.global [%0], [%1], 8;"
                 :: "r"(dst), "l"(__cvta_generic_to_global(src)) : "memory");
}
#define CP_COMMIT() asm volatile("cp.async.commit_group;" ::: "memory")
#define CP_WAIT1()  asm volatile("cp.async.wait_group 1;" ::: "memory")
#define CP_WAIT0()  asm volatile("cp.async.wait_group 0;" ::: "memory")

__global__ void init_kernel() {
    int i = blockIdx.x * blockDim.x + threadIdx.x;
    if (i < PADMAX) g_sorted_token[i] = 0;
    if (i < EE) { g_count[i] = 0; g_fill[i] = 0; g_psum[i] = 0.f; }
}

__global__ void router_kernel(const float* __restrict__ x, const float* __restrict__ rw) {
    int t = blockIdx.x;
    __shared__ float sp[128][EE];
    float acc[EE];
#pragma unroll
    for (int e = 0; e < EE; e++) acc[e] = 0.f;
    const float* xt = x + (size_t)t * HH;
    for (int h = threadIdx.x; h < HH; h += 128) {
        float xv = xt[h];
#pragma unroll
        for (int e = 0; e < EE; e++) acc[e] += xv * rw[e*HH + h];
    }
#pragma unroll
    for (int e = 0; e < EE; e++) sp[threadIdx.x][e] = acc[e];
    __syncthreads();
    for (int s = 64; s > 0; s >>= 1) {
        if (threadIdx.x < s)
#pragma unroll
            for (int e = 0; e < EE; e++) sp[threadIdx.x][e] += sp[threadIdx.x + s][e];
        __syncthreads();
    }
    if (threadIdx.x == 0) {
        float lg[EE];
#pragma unroll
        for (int e = 0; e < EE; e++) lg[e] = sp[0][e];
        int i0 = 0;
#pragma unroll
        for (int e = 1; e < EE; e++) if (lg[e] > lg[i0]) i0 = e;
        int i1 = -1;
#pragma unroll
        for (int e = 0; e < EE; e++) {
            if (e == i0) continue;
            if (i1 < 0 || lg[e] > lg[i1]) i1 = e;
        }
        float ex = expf(lg[i1] - lg[i0]);
        g_tok_e[2*t] = i0;  g_tok_e[2*t+1] = i1;
        g_tok_w[2*t] = 1.f/(1.f+ex);  g_tok_w[2*t+1] = ex/(1.f+ex);
        atomicAdd(&g_count[i0], 1);
        atomicAdd(&g_count[i1], 1);
        float m = lg[0];
#pragma unroll
        for (int e = 1; e < EE; e++) m = fmaxf(m, lg[e]);
        float s = 0.f, pe[EE];
#pragma unroll
        for (int e = 0; e < EE; e++) { pe[e] = expf(lg[e] - m); s += pe[e]; }
        float inv = 1.f / s;
#pragma unroll
        for (int e = 0; e < EE; e++) atomicAdd(&g_psum[e], pe[e] * inv);
    }
}

__global__ void setup_kernel(float* __restrict__ out_aux) {
    if (threadIdx.x == 0) {
        int base = 0;
        for (int e = 0; e < EE; e++) {
            g_base[e] = base;
            base += (g_count[e] + BM - 1) & ~(BM - 1);
        }
        g_base[EE] = base;
        float aux = 0.f;
        for (int e = 0; e < EE; e++)
            aux += ((float)g_count[e] / SLOTS) * (g_psum[e] / TT);
        out_aux[0] = aux * EE;
    }
}

__global__ void scatter_kernel() {
    int s = blockIdx.x * blockDim.x + threadIdx.x;
    if (s >= SLOTS) return;
    int e = g_tok_e[s];
    int row = g_base[e] + atomicAdd(&g_fill[e], 1);
    g_sorted_token[row] = s >> 1;
    g_slot_row[s] = row;
}

// ---- pack kernels: fp32 -> (hi,lo) bf16x2 pair format ----
__global__ void pack_x_kernel(const float* __restrict__ x) {
    size_t i = (size_t)blockIdx.x * blockDim.x + threadIdx.x;
    if (i >= (size_t)TT * KP_H) return;
    float2 v = ((const float2*)x)[i];
    g_px[i] = spb(v.x, v.y);
}

// pwgu[e][kp][2f]=gate(f), [2f+1]=up(f)
__global__ void pack_wgu_kernel(const float* __restrict__ wg, const float* __restrict__ wu) {
    size_t i = (size_t)blockIdx.x * blockDim.x + threadIdx.x;
    if (i >= (size_t)EE * KP_H * FF) return;
    int f = (int)(i % FF);
    size_t ek = i / FF;
    int kp = (int)(ek % KP_H);
    int e = (int)(ek / KP_H);
    size_t src = ((size_t)e * HH + 2*kp) * FF + f;
    uint2 pg = spb(wg[src], wg[src + FF]);
    uint2 pu = spb(wu[src], wu[src + FF]);
    size_t dst = ek * (2*FF) + 2*f;
    *(uint4*)&g_pwgu[dst] = make_uint4(pg.x, pg.y, pu.x, pu.y);
}

__global__ void pack_wd_kernel(const float* __restrict__ wd) {
    size_t i = (size_t)blockIdx.x * blockDim.x + threadIdx.x;
    if (i >= (size_t)EE * KP_F * HH) return;
    int h = (int)(i % HH);
    size_t ek = i / HH;
    int kp = (int)(ek % KP_F);
    int e = (int)(ek / KP_F);
    size_t src = ((size_t)e * FF + 2*kp) * HH + h;
    g_pwd[i] = spb(wd[src], wd[src + HH]);
}

__global__ void pack_h1_kernel() {
    size_t i = (size_t)blockIdx.x * blockDim.x + threadIdx.x;
    if (i >= (size_t)PADMAX * KP_F) return;
    int row = (int)(i / KP_F);
    if (row >= g_base[EE]) return;
    int kp = (int)(i % KP_F);
    float2 v = *(const float2*)&g_h1[(size_t)row * FF + 2*kp];
    g_ph1[i] = spb(v.x, v.y);
}

// ==== GEMM1: h1 = silu(x@Wg)*(x@Wu). 256 thr, CTA 128M x 64F (gate/up interleaved) ====
__global__ __launch_bounds__(256, 2) void gemm1_kernel() {
    int r0 = blockIdx.x * BM;
    if (r0 >= g_base[EE]) return;
    int n0f = blockIdx.y * 64;
    int e = 0;
    while (g_base[e+1] <= r0) e++;

    __shared__ __align__(16) uint2 As[2][8][PIT];
    __shared__ __align__(16) uint2 Bs[2][8][PIT];
    __shared__ int s_tok[128];

    int tid = threadIdx.x, lane = tid & 31, wid = tid >> 5;
    if (tid < 128) s_tok[tid] = g_sorted_token[r0 + tid];
    __syncthreads();

    int wm = (wid >> 1) * 32, wn = (wid & 1) * 64;
    int fr = lane >> 2, kq = lane & 3;

    int a_row = tid & 127, a_kh = tid >> 7;      // a_kh in {0,1}
    int b_kp = tid >> 5, b_c = (tid & 31) * 4;   // B: row kp, 4 cols

    const uint2* abase = g_px + (size_t)s_tok[a_row] * KP_H + a_kh * 4;
    const uint2* bbase = g_pwgu + (size_t)e * KP_H * (2*FF) + 2*n0f + b_c;

    float d[2][8][4];
#pragma unroll
    for (int i = 0; i < 2; i++)
#pragma unroll
        for (int j = 0; j < 8; j++)
#pragma unroll
            for (int k = 0; k < 4; k++) d[i][j][k] = 0.f;

#define G1_LOAD(cc, st) do {                                                   \
    const uint2* as_ = abase + (size_t)(cc) * 8;                               \
    uint32_t ad_ = smem_u32(&As[st][a_kh*4][a_row]);                           \
    cp8(ad_,             as_);                                                 \
    cp8(ad_ + PIT*8,     as_ + 1);                                             \
    cp8(ad_ + 2*PIT*8,   as_ + 2);                                             \
    cp8(ad_ + 3*PIT*8,   as_ + 3);                                             \
    const uint2* bs_ = bbase + ((size_t)(cc) * 8 + b_kp) * (2*FF);             \
    uint32_t bd_ = smem_u32(&Bs[st][b_kp][b_c]);                               \
    cp16(bd_,      bs_);                                                       \
    cp16(bd_ + 16, bs_ + 2);                                                   \
    CP_COMMIT();                                                               \
} while (0)

    G1_LOAD(0, 0);
    G1_LOAD(1, 1);

    const int chunks = HH / 16;   // 64
    for (int c = 0; c < chunks; c++) {
        int s = c & 1;
        if (c + 1 >= chunks) CP_WAIT0(); else CP_WAIT1();
        __syncthreads();
        uint32_t ahi[2][4], alo[2][4];
#pragma unroll
        for (int mt = 0; mt < 2; mt++) {
            int mb = wm + mt*16 + fr;
            uint2 q0 = As[s][kq][mb],   q1 = As[s][kq][mb+8];
            uint2 q2 = As[s][kq+4][mb], q3 = As[s][kq+4][mb+8];
            ahi[mt][0]=q0.x; ahi[mt][1]=q1.x; ahi[mt][2]=q2.x; ahi[mt][3]=q3.x;
            alo[mt][0]=q0.y; alo[mt][1]=q1.y; alo[mt][2]=q2.y; alo[mt][3]=q3.y;
        }
#pragma unroll
        for (int nt = 0; nt < 8; nt++) {
            int nn = wn + nt*8 + fr;
            uint2 b0 = Bs[s][kq][nn], b1 = Bs[s][kq+4][nn];
#pragma unroll
            for (int mt = 0; mt < 2; mt++) {
                mma_bf16(d[mt][nt], ahi[mt], b0.x, b1.x);
                mma_bf16(d[mt][nt], ahi[mt], b0.y, b1.y);
                mma_bf16(d[mt][nt], alo[mt], b0.x, b1.x);
            }
        }
        __syncthreads();
        if (c + 2 < chunks) G1_LOAD(c + 2, s);
    }
#undef G1_LOAD

#pragma unroll
    for (int mt = 0; mt < 2; mt++) {
        int row = r0 + wm + mt*16 + fr;
#pragma unroll
        for (int nt = 0; nt < 8; nt++) {
            int f = n0f + (wn >> 1) + nt*4 + kq;
            float gv = d[mt][nt][0], uv = d[mt][nt][1];
            g_h1[(size_t)row * FF + f] = (gv / (1.f + expf(-gv))) * uv;
            gv = d[mt][nt][2]; uv = d[mt][nt][3];
            g_h1[(size_t)(row + 8) * FF + f] = (gv / (1.f + expf(-gv))) * uv;
        }
    }
}

// ==== GEMM2: y = h1 @ Wd. 256 thr, CTA 128M x 128N ====
__global__ __launch_bounds__(256, 2) void gemm2_kernel() {
    int r0 = blockIdx.x * BM;
    if (r0 >= g_base[EE]) return;
    int n0 = blockIdx.y * 128;
    int e = 0;
    while (g_base[e+1] <= r0) e++;

    __shared__ __align__(16) uint2 As[2][8][PIT];
    __shared__ __align__(16) uint2 Bs[2][8][PIT];

    int tid = threadIdx.x, lane = tid & 31, wid = tid >> 5;
    int wm = (wid >> 1) * 32, wn = (wid & 1) * 64;
    int fr = lane >> 2, kq = lane & 3;

    int a_row = tid & 127, a_kh = tid >> 7;
    int b_kp = tid >> 5, b_c = (tid & 31) * 4;

    const uint2* abase = g_ph1 + (size_t)(r0 + a_row) * KP_F + a_kh * 4;
    const uint2* bbase = g_pwd + (size_t)e * KP_F * HH + n0 + b_c;

    float d[2][8][4];
#pragma unroll
    for (int i = 0; i < 2; i++)
#pragma unroll
        for (int j = 0; j < 8; j++)
#pragma unroll
            for (int k = 0; k < 4; k++) d[i][j][k] = 0.f;

#define G2_LOAD(cc, st) do {                                                   \
    const uint2* as_ = abase + (size_t)(cc) * 8;                               \
    uint32_t ad_ = smem_u32(&As[st][a_kh*4][a_row]);                           \
    cp8(ad_,             as_);                                                 \
    cp8(ad_ + PIT*8,     as_ + 1);                                             \
    cp8(ad_ + 2*PIT*8,   as_ + 2);                                             \
    cp8(ad_ + 3*PIT*8,   as_ + 3);                                             \
    const uint2* bs_ = bbase + ((size_t)(cc) * 8 + b_kp) * HH;                 \
    uint32_t bd_ = smem_u32(&Bs[st][b_kp][b_c]);                               \
    cp16(bd_,      bs_);                                                       \
    cp16(bd_ + 16, bs_ + 2);                                                   \
    CP_COMMIT();                                                               \
} while (0)

    G2_LOAD(0, 0);
    G2_LOAD(1, 1);

    const int chunks = FF / 16;   // 176
    for (int c = 0; c < chunks; c++) {
        int s = c & 1;
        if (c + 1 >= chunks) CP_WAIT0(); else CP_WAIT1();
        __syncthreads();
        uint32_t ahi[2][4], alo[2][4];
#pragma unroll
        for (int mt = 0; mt < 2; mt++) {
            int mb = wm + mt*16 + fr;
            uint2 q0 = As[s][kq][mb],   q1 = As[s][kq][mb+8];
            uint2 q2 = As[s][kq+4][mb], q3 = As[s][kq+4][mb+8];
            ahi[mt][0]=q0.x; ahi[mt][1]=q1.x; ahi[mt][2]=q2.x; ahi[mt][3]=q3.x;
            alo[mt][0]=q0.y; alo[mt][1]=q1.y; alo[mt][2]=q2.y; alo[mt][3]=q3.y;
        }
#pragma unroll
        for (int nt = 0; nt < 8; nt++) {
            int nn = wn + nt*8 + fr;
            uint2 b0 = Bs[s][kq][nn], b1 = Bs[s][kq+4][nn];
#pragma unroll
            for (int mt = 0; mt < 2; mt++) {
                mma_bf16(d[mt][nt], ahi[mt], b0.x, b1.x);
                mma_bf16(d[mt][nt], ahi[mt], b0.y, b1.y);
                mma_bf16(d[mt][nt], alo[mt], b0.x, b1.x);
            }
        }
        __syncthreads();
        if (c + 2 < chunks) G2_LOAD(c + 2, s);
    }
#undef G2_LOAD

#pragma unroll
    for (int mt = 0; mt < 2; mt++) {
        int row = r0 + wm + mt*16 + fr;
#pragma unroll
        for (int nt = 0; nt < 8; nt++) {
            int col = n0 + wn + nt*8 + 2*kq;
            *(float2*)&g_y[(size_t)row * HH + col]       = make_float2(d[mt][nt][0], d[mt][nt][1]);
            *(float2*)&g_y[(size_t)(row + 8) * HH + col] = make_float2(d[mt][nt][2], d[mt][nt][3]);
        }
    }
}

__global__ void combine_kernel(float* __restrict__ out) {
    int i = blockIdx.x * blockDim.x + threadIdx.x;
    if (i >= TT * (HH/4)) return;
    int t = i / (HH/4);
    int c = (i - t * (HH/4)) * 4;
    int r0 = g_slot_row[2*t], r1 = g_slot_row[2*t+1];
    float w0 = g_tok_w[2*t], w1 = g_tok_w[2*t+1];
    float4 y0 = *(const float4*)(g_y + (size_t)r0 * HH + c);
    float4 y1 = *(const float4*)(g_y + (size_t)r1 * HH + c);
    float4 o;
    o.x = w0*y0.x + w1*y1.x;  o.y = w0*y0.y + w1*y1.y;
    o.z = w0*y0.z + w1*y1.z;  o.w = w0*y0.w + w1*y1.w;
    *(float4*)(out + (size_t)t * HH + c) = o;
}

extern "C" void kernel_launch(void* const* d_in, const int* in_sizes, int n_in,
                              void* d_out, int out_size) {
    const float* x  = (const float*)d_in[0];
    const float* rw = (const float*)d_in[1];
    const float* wg = (const float*)d_in[2];
    const float* wu = (const float*)d_in[3];
    const float* wd = (const float*)d_in[4];
    float* out = (float*)d_out;

    init_kernel<<<(PADMAX + 255) / 256, 256>>>();
    router_kernel<<<TT, 128>>>(x, rw);
    setup_kernel<<<1, 32>>>(out + (size_t)TT * HH);
    scatter_kernel<<<(SLOTS + 255) / 256, 256>>>();
    pack_x_kernel<<<(int)(((size_t)TT*KP_H + 255) / 256), 256>>>(x);
    pack_wgu_kernel<<<(int)(((size_t)EE*KP_H*FF + 255) / 256), 256>>>(wg, wu);
    pack_wd_kernel<<<(int)(((size_t)EE*KP_F*HH + 255) / 256), 256>>>(wd);
    gemm1_kernel<<<dim3(RT_MAX, FF/64), 256>>>();
    pack_h1_kernel<<<(int)(((size_t)PADMAX*KP_F + 255) / 256), 256>>>();
    gemm2_kernel<<<dim3(RT_MAX, HH/128), 256>>>();
    combine_kernel<<<(TT * (HH/4) + 255) / 256, 256>>>(out);
}